// round 2
// baseline (speedup 1.0000x reference)
#include <cuda_runtime.h>
#include <cuda_bf16.h>

#define O_   4
#define N_   3072
#define KNN  10
#define TOLC 0.01f

// ---------------- device scratch (no allocations allowed) ----------------
__device__ float4 g_T[O_][3];          // per-object rows: (R_r0, R_r1, R_r2, t_r)
__device__ float4 g_pip4[O_ * N_];     // transformed point: (x, y, z, |p|^2)
__device__ float4 g_nrm4[O_ * N_];     // raw normal: (nx, ny, nz, 0)
__device__ float  g_scr[O_][3][N_];    // signed nearest distance per (b, other-idx, n)

// ---------------- kernel 1: T = inv(T_plane) @ T_obj ----------------
__global__ void prep_kernel(const float* __restrict__ T_obj,
                            const float* __restrict__ T_plane) {
    int o = threadIdx.x;
    if (o >= O_) return;
    float Rp[9], tp[3];
    #pragma unroll
    for (int r = 0; r < 3; r++) {
        #pragma unroll
        for (int c = 0; c < 3; c++) Rp[r * 3 + c] = T_plane[r * 4 + c];
        tp[r] = T_plane[r * 4 + 3];
    }
    const float* To = T_obj + o * 16;
    // inv(T_plane) rigid: [Rp^T | -Rp^T tp].  R = Rp^T Ro ; t = Rp^T (to - tp)
    #pragma unroll
    for (int r = 0; r < 3; r++) {
        float R0 = Rp[0 + r] * To[0] + Rp[3 + r] * To[4] + Rp[6 + r] * To[8];
        float R1 = Rp[0 + r] * To[1] + Rp[3 + r] * To[5] + Rp[6 + r] * To[9];
        float R2 = Rp[0 + r] * To[2] + Rp[3 + r] * To[6] + Rp[6 + r] * To[10];
        float tr = Rp[0 + r] * (To[3] - tp[0]) + Rp[3 + r] * (To[7] - tp[1])
                 + Rp[6 + r] * (To[11] - tp[2]);
        g_T[o][r] = make_float4(R0, R1, R2, tr);
    }
}

// ---------------- kernel 2: transform points, pack float4 ----------------
__global__ void transform_kernel(const float* __restrict__ points) {
    int i = blockIdx.x * blockDim.x + threadIdx.x;
    if (i >= O_ * N_) return;
    int o = i / N_;
    const float* p = points + (size_t)i * 6;
    float x = p[0], y = p[1], z = p[2];
    float4 r0 = g_T[o][0], r1 = g_T[o][1], r2 = g_T[o][2];
    float px = fmaf(r0.x, x, fmaf(r0.y, y, fmaf(r0.z, z, r0.w)));
    float py = fmaf(r1.x, x, fmaf(r1.y, y, fmaf(r1.z, z, r1.w)));
    float pz = fmaf(r2.x, x, fmaf(r2.y, y, fmaf(r2.z, z, r2.w)));
    float rr = px * px + py * py + pz * pz;
    g_pip4[i] = make_float4(px, py, pz, rr);
    g_nrm4[i] = make_float4(p[3], p[4], p[5], 0.f);
}

// ordered-float: monotone bijection float bits -> unsigned
__device__ __forceinline__ unsigned f2ord(float f) {
    unsigned b = __float_as_uint(f);
    return b ^ ((unsigned)(((int)b) >> 31) | 0x80000000u);
}
__device__ __forceinline__ float ord2f(unsigned u) {
    int ib = (u & 0x80000000u) ? (int)(u ^ 0x80000000u) : ~(int)u;
    return __int_as_float(ib);
}

// ---------------- kernel 3: brute-force exact top-10 per (b, o!=b, n) ----------------
// blockIdx.y = pair (b * 3 + oi), blockIdx.x = query chunk of 128
__global__ void __launch_bounds__(128) knn_kernel() {
    extern __shared__ float4 sh[];     // N_ candidate float4 of object o
    int pair = blockIdx.y;
    int b  = pair / 3;
    int oi = pair % 3;
    int o  = oi + (oi >= b ? 1 : 0);
    int n  = blockIdx.x * blockDim.x + threadIdx.x;

    const float4* cand = g_pip4 + o * N_;
    for (int i = threadIdx.x; i < N_; i += blockDim.x) sh[i] = cand[i];
    __syncthreads();

    float4 q = g_pip4[b * N_ + n];
    float m2x = -2.f * q.x, m2y = -2.f * q.y, m2z = -2.f * q.z;

    // top-10 64-bit keys: (ordered_float(d_partial) << 32) | candidate_index
    // sentinel = ordered(FLT_MAX) in high word so reconstructed threshold is finite
    unsigned long long a[KNN];
    #pragma unroll
    for (int s = 0; s < KNN; s++) a[s] = 0xFF7FFFFFFFFFFFFFull;
    float thresh = __int_as_float(0x7F800000);  // +inf

    #pragma unroll 4
    for (int j = 0; j < N_; j++) {
        float4 c = sh[j];
        // d_partial = |c|^2 - 2 q.c   (monotone in true squared distance)
        float d = fmaf(c.x, m2x, fmaf(c.y, m2y, fmaf(c.z, m2z, c.w)));
        if (d < thresh) {
            unsigned long long t =
                ((unsigned long long)f2ord(d) << 32) | (unsigned)j;
            #pragma unroll
            for (int s = 0; s < KNN; s++) {
                unsigned long long lo = (a[s] < t) ? a[s] : t;
                t = (a[s] < t) ? t : a[s];
                a[s] = lo;
            }
            thresh = ord2f((unsigned)(a[KNN - 1] >> 32));
        }
    }

    // exact nearest distance from winning index
    unsigned i0 = (unsigned)(a[0] & 0xFFFFFFFFu);
    float4 c0 = sh[i0];
    float D = q.w + fmaf(c0.x, m2x, fmaf(c0.y, m2y, fmaf(c0.z, m2z, c0.w)));
    float d0 = sqrtf(fmaxf(D, 0.f));

    // inside test: count over 10 NN of sign(dot(raw normal, near - p)) > 0
    int cnt = 0;
    const float4* nrm = g_nrm4 + o * N_;
    #pragma unroll
    for (int s = 0; s < KNN; s++) {
        unsigned id = (unsigned)(a[s] & 0xFFFFFFFFu);
        float4 c = sh[id];
        float4 m = nrm[id];
        float dt = (c.x - q.x) * m.x + (c.y - q.y) * m.y + (c.z - q.z) * m.z;
        cnt += (dt > 0.f) ? 1 : 0;
    }
    float sd = (cnt > 8) ? -d0 : d0;    // sum(insides) > 0.8*k  ->  >= 9
    g_scr[b][oi][n] = sd;
}

// ---------------- kernel 4: min over other objects + plane, write out ----------------
__global__ void finalize_kernel(float* __restrict__ out, int out_size) {
    int i = blockIdx.x * blockDim.x + threadIdx.x;
    if (i >= O_ * N_) return;
    int b = i / N_;
    int n = i % N_;
    float sd = g_pip4[i].z;                 // plane signed distance = pip.z
    sd = fminf(sd, g_scr[b][0][n]);
    sd = fminf(sd, g_scr[b][1][n]);
    sd = fminf(sd, g_scr[b][2][n]);
    out[i] = sd;
    if (out_size >= 2 * O_ * N_)
        out[O_ * N_ + i] = (sd < -TOLC) ? 1.0f : 0.0f;
}

// ---------------- launch ----------------
extern "C" void kernel_launch(void* const* d_in, const int* in_sizes, int n_in,
                              void* d_out, int out_size) {
    // map inputs by element count: points=73728, T_obj=64, T_plane=16
    const float* points  = nullptr;
    const float* T_obj   = nullptr;
    const float* T_plane = nullptr;
    for (int i = 0; i < n_in; i++) {
        if (in_sizes[i] == O_ * N_ * 6) points  = (const float*)d_in[i];
        else if (in_sizes[i] == 64)     T_obj   = (const float*)d_in[i];
        else if (in_sizes[i] == 16)     T_plane = (const float*)d_in[i];
    }

    prep_kernel<<<1, 32>>>(T_obj, T_plane);
    transform_kernel<<<(O_ * N_ + 255) / 256, 256>>>(points);

    (void)cudaFuncSetAttribute(knn_kernel,
                               cudaFuncAttributeMaxDynamicSharedMemorySize,
                               N_ * (int)sizeof(float4));
    knn_kernel<<<dim3(N_ / 128, O_ * 3), 128, N_ * sizeof(float4)>>>();

    finalize_kernel<<<(O_ * N_ + 255) / 256, 256>>>((float*)d_out, out_size);
}

// round 3
// speedup vs baseline: 1.6534x; 1.6534x over previous
#include <cuda_runtime.h>
#include <cuda_bf16.h>

#define O_    4
#define N_    3072
#define KNN   10
#define TOLC  0.01f
#define FMAXV 3.402823466e+38f
#define CAP   128            // per-thread trigger buffer entries (E[57], Poisson tail << 1e-12)
#define BTHR  128            // threads per knn block

// ---------------- device scratch (no allocations allowed) ----------------
__device__ float4 g_pip4[O_ * N_];     // transformed point: (x, y, z, |p|^2)
__device__ float4 g_nrm4[O_ * N_];     // raw normal: (nx, ny, nz, 0)
__device__ float  g_scr[O_][3][N_];    // signed nearest distance per (b, other-idx, n)

// ---------------- kernel 1: prep + transform fused ----------------
// Each thread redundantly computes T = inv(T_plane) @ T_obj[o] (~40 FMA, trivial),
// then transforms its point and packs (x,y,z,|p|^2) and the raw normal.
__global__ void transform_kernel(const float* __restrict__ points,
                                 const float* __restrict__ T_obj,
                                 const float* __restrict__ T_plane) {
    int i = blockIdx.x * blockDim.x + threadIdx.x;
    if (i >= O_ * N_) return;
    int o = i / N_;

    float Rp[9], tp[3];
    #pragma unroll
    for (int r = 0; r < 3; r++) {
        #pragma unroll
        for (int c = 0; c < 3; c++) Rp[r * 3 + c] = __ldg(&T_plane[r * 4 + c]);
        tp[r] = __ldg(&T_plane[r * 4 + 3]);
    }
    const float* To = T_obj + o * 16;
    // inv(T_plane) rigid: [Rp^T | -Rp^T tp].  Row r: R = Rp^T Ro ; t = Rp^T (to - tp)
    float R[3][3], tr[3];
    #pragma unroll
    for (int r = 0; r < 3; r++) {
        R[r][0] = Rp[0 + r] * To[0] + Rp[3 + r] * To[4] + Rp[6 + r] * To[8];
        R[r][1] = Rp[0 + r] * To[1] + Rp[3 + r] * To[5] + Rp[6 + r] * To[9];
        R[r][2] = Rp[0 + r] * To[2] + Rp[3 + r] * To[6] + Rp[6 + r] * To[10];
        tr[r]   = Rp[0 + r] * (To[3] - tp[0]) + Rp[3 + r] * (To[7] - tp[1])
                + Rp[6 + r] * (To[11] - tp[2]);
    }

    const float* p = points + (size_t)i * 6;
    float x = p[0], y = p[1], z = p[2];
    float px = fmaf(R[0][0], x, fmaf(R[0][1], y, fmaf(R[0][2], z, tr[0])));
    float py = fmaf(R[1][0], x, fmaf(R[1][1], y, fmaf(R[1][2], z, tr[1])));
    float pz = fmaf(R[2][0], x, fmaf(R[2][1], y, fmaf(R[2][2], z, tr[2])));
    float rr = px * px + py * py + pz * pz;
    g_pip4[i] = make_float4(px, py, pz, rr);
    g_nrm4[i] = make_float4(p[3], p[4], p[5], 0.f);
}

// ---------------- kernel 2: brute-force exact top-10 per (b, o!=b, n) ----------------
// blockIdx.y = pair (b*3 + oi), blockIdx.x = query chunk of BTHR
// smem: [0, 48KB)  candidate float4 of object o
//       [48KB, +64KB) per-thread trigger index buffer, interleaved u32 (conflict-free)
__global__ void __launch_bounds__(BTHR) knn_kernel() {
    extern __shared__ float4 sh[];
    unsigned* buf = (unsigned*)(sh + N_);          // buf[c*BTHR + tid]
    int pair = blockIdx.y;
    int b  = pair / 3;
    int oi = pair % 3;
    int o  = oi + (oi >= b ? 1 : 0);
    int tid = threadIdx.x;
    int n  = blockIdx.x * BTHR + tid;

    const float4* cand = g_pip4 + o * N_;
    for (int i = tid; i < N_; i += BTHR) sh[i] = cand[i];
    __syncthreads();

    float4 q = g_pip4[b * N_ + n];
    float m2x = -2.f * q.x, m2y = -2.f * q.y, m2z = -2.f * q.z;

    // ascending float-only top-10 (registers), plus deferred index triggers in smem
    float a[KNN];
    #pragma unroll
    for (int s = 0; s < KNN; s++) a[s] = FMAXV;
    float thresh = FMAXV;
    int cnt = 0;

    #pragma unroll 1
    for (int j0 = 0; j0 < N_; j0 += 8) {
        float d[8];
        #pragma unroll
        for (int u = 0; u < 8; u++) {
            float4 c = sh[j0 + u];
            // d_partial = |c|^2 - 2 q.c  (monotone in squared distance)
            d[u] = fmaf(c.x, m2x, fmaf(c.y, m2y, fmaf(c.z, m2z, c.w)));
        }
        #pragma unroll
        for (int u = 0; u < 8; u++) {
            if (d[u] < thresh) {
                float t = d[u];
                #pragma unroll
                for (int s = 0; s < KNN; s++) {
                    float lo = fminf(a[s], t);
                    t = fmaxf(a[s], t);
                    a[s] = lo;
                }
                thresh = a[KNN - 1];
                if (cnt < CAP) buf[cnt * BTHR + tid] = (unsigned)(j0 + u);
                cnt++;
            }
        }
    }

    // filter triggers against exact final threshold, compact to first KNN (index order)
    unsigned idx[1];  // not used; final ids kept in smem slots 0..KNN-1
    int w = 0;
    int m = cnt < CAP ? cnt : CAP;
    for (int t = 0; t < m; t++) {
        unsigned id = buf[t * BTHR + tid];
        float4 c = sh[id];
        float d = fmaf(c.x, m2x, fmaf(c.y, m2y, fmaf(c.z, m2z, c.w)));
        if (d <= thresh && w < KNN) { buf[w * BTHR + tid] = id; w++; }
    }
    if (cnt > CAP) {   // overflow fallback: exact rescan (never taken in practice)
        w = 0;
        for (int j = 0; j < N_ && w < KNN; j++) {
            float4 c = sh[j];
            float d = fmaf(c.x, m2x, fmaf(c.y, m2y, fmaf(c.z, m2z, c.w)));
            if (d <= thresh) { buf[w * BTHR + tid] = (unsigned)j; w++; }
        }
    }

    // exact nearest distance (a[0] = min partial, computed identically to reference path)
    float D = q.w + a[0];
    float d0 = sqrtf(fmaxf(D, 0.f));

    // inside test: count over 10 NN of sign(dot(raw normal, near - p)) > 0
    int votes = 0;
    const float4* nrm = g_nrm4 + o * N_;
    #pragma unroll
    for (int s = 0; s < KNN; s++) {
        unsigned id = buf[s * BTHR + tid];
        float4 c = sh[id];
        float4 nm = __ldg(&nrm[id]);
        float dt = (c.x - q.x) * nm.x + (c.y - q.y) * nm.y + (c.z - q.z) * nm.z;
        votes += (dt > 0.f) ? 1 : 0;
    }
    float sd = (votes > 8) ? -d0 : d0;    // sum(insides) > 0.8*k  ->  >= 9
    g_scr[b][oi][n] = sd;
    (void)idx;
}

// ---------------- kernel 3: min over other objects + plane, write out ----------------
__global__ void finalize_kernel(float* __restrict__ out, int out_size) {
    int i = blockIdx.x * blockDim.x + threadIdx.x;
    if (i >= O_ * N_) return;
    int b = i / N_;
    int n = i % N_;
    float sd = g_pip4[i].z;                 // plane signed distance = pip.z
    sd = fminf(sd, g_scr[b][0][n]);
    sd = fminf(sd, g_scr[b][1][n]);
    sd = fminf(sd, g_scr[b][2][n]);
    out[i] = sd;
    if (out_size >= 2 * O_ * N_)
        out[O_ * N_ + i] = (sd < -TOLC) ? 1.0f : 0.0f;
}

// ---------------- launch ----------------
extern "C" void kernel_launch(void* const* d_in, const int* in_sizes, int n_in,
                              void* d_out, int out_size) {
    // map inputs by element count: points=73728, T_obj=64, T_plane=16
    const float* points  = nullptr;
    const float* T_obj   = nullptr;
    const float* T_plane = nullptr;
    for (int i = 0; i < n_in; i++) {
        if (in_sizes[i] == O_ * N_ * 6) points  = (const float*)d_in[i];
        else if (in_sizes[i] == 64)     T_obj   = (const float*)d_in[i];
        else if (in_sizes[i] == 16)     T_plane = (const float*)d_in[i];
    }

    transform_kernel<<<(O_ * N_ + 255) / 256, 256>>>(points, T_obj, T_plane);

    int smem = N_ * (int)sizeof(float4) + CAP * BTHR * (int)sizeof(unsigned);
    (void)cudaFuncSetAttribute(knn_kernel,
                               cudaFuncAttributeMaxDynamicSharedMemorySize, smem);
    knn_kernel<<<dim3(N_ / BTHR, O_ * 3), BTHR, smem>>>();

    finalize_kernel<<<(O_ * N_ + 255) / 256, 256>>>((float*)d_out, out_size);
}

// round 4
// speedup vs baseline: 1.9163x; 1.1590x over previous
#include <cuda_runtime.h>
#include <cuda_bf16.h>

#define O_    4
#define N_    3072
#define KNN   10
#define TOLC  0.01f
#define FMAXV 3.402823466e+38f
#define NSPL  2              // candidate splits
#define LSPL  (N_ / NSPL)    // 1536 candidates per split
#define CAP   120            // per-thread trigger buffer entries (E~60, 8 sigma margin)
#define BTHR  128            // threads per knn block

// ---------------- device scratch (no allocations allowed) ----------------
__device__ float4 g_pip4[O_ * N_];                 // (x, y, z, |p|^2)
__device__ float4 g_nrm4[O_ * N_];                 // raw normal
__device__ unsigned long long g_part[O_ * 3][NSPL][KNN][N_];  // sorted partial keys

// ordered-float helpers: monotone bijection float <-> unsigned
__device__ __forceinline__ unsigned f2ord(float f) {
    unsigned b = __float_as_uint(f);
    return b ^ ((unsigned)(((int)b) >> 31) | 0x80000000u);
}
__device__ __forceinline__ float ord2f(unsigned u) {
    int ib = (u & 0x80000000u) ? (int)(u ^ 0x80000000u) : ~(int)u;
    return __int_as_float(ib);
}

// ---------------- kernel 1: prep + transform fused ----------------
__global__ void transform_kernel(const float* __restrict__ points,
                                 const float* __restrict__ T_obj,
                                 const float* __restrict__ T_plane) {
    int i = blockIdx.x * blockDim.x + threadIdx.x;
    if (i >= O_ * N_) return;
    int o = i / N_;

    float Rp[9], tp[3];
    #pragma unroll
    for (int r = 0; r < 3; r++) {
        #pragma unroll
        for (int c = 0; c < 3; c++) Rp[r * 3 + c] = __ldg(&T_plane[r * 4 + c]);
        tp[r] = __ldg(&T_plane[r * 4 + 3]);
    }
    const float* To = T_obj + o * 16;
    // inv(T_plane) rigid: [Rp^T | -Rp^T tp]
    float R[3][3], tr[3];
    #pragma unroll
    for (int r = 0; r < 3; r++) {
        R[r][0] = Rp[0 + r] * To[0] + Rp[3 + r] * To[4] + Rp[6 + r] * To[8];
        R[r][1] = Rp[0 + r] * To[1] + Rp[3 + r] * To[5] + Rp[6 + r] * To[9];
        R[r][2] = Rp[0 + r] * To[2] + Rp[3 + r] * To[6] + Rp[6 + r] * To[10];
        tr[r]   = Rp[0 + r] * (To[3] - tp[0]) + Rp[3 + r] * (To[7] - tp[1])
                + Rp[6 + r] * (To[11] - tp[2]);
    }

    const float* p = points + (size_t)i * 6;
    float x = p[0], y = p[1], z = p[2];
    float px = fmaf(R[0][0], x, fmaf(R[0][1], y, fmaf(R[0][2], z, tr[0])));
    float py = fmaf(R[1][0], x, fmaf(R[1][1], y, fmaf(R[1][2], z, tr[1])));
    float pz = fmaf(R[2][0], x, fmaf(R[2][1], y, fmaf(R[2][2], z, tr[2])));
    float rr = px * px + py * py + pz * pz;
    g_pip4[i] = make_float4(px, py, pz, rr);
    g_nrm4[i] = make_float4(p[3], p[4], p[5], 0.f);
}

// ---------------- kernel 2: partial exact top-10 over one candidate split ----------------
// blockIdx = (query chunk, pair, split)
__global__ void __launch_bounds__(BTHR) knn_partial_kernel() {
    extern __shared__ float4 sh[];                     // LSPL candidate float4
    unsigned short* buf = (unsigned short*)(sh + LSPL); // buf[c*BTHR + tid], local idx
    int pair = blockIdx.y;
    int spl  = blockIdx.z;
    int b  = pair / 3;
    int oi = pair % 3;
    int o  = oi + (oi >= b ? 1 : 0);
    int tid = threadIdx.x;
    int n  = blockIdx.x * BTHR + tid;
    int jbase = spl * LSPL;

    const float4* cand = g_pip4 + o * N_ + jbase;
    for (int i = tid; i < LSPL; i += BTHR) sh[i] = cand[i];
    __syncthreads();

    float4 q = g_pip4[b * N_ + n];
    float m2x = -2.f * q.x, m2y = -2.f * q.y, m2z = -2.f * q.z;

    float a[KNN];
    #pragma unroll
    for (int s = 0; s < KNN; s++) a[s] = FMAXV;
    float thresh = FMAXV;
    int cnt = 0;

    #pragma unroll 1
    for (int j0 = 0; j0 < LSPL; j0 += 8) {
        float d[8];
        #pragma unroll
        for (int u = 0; u < 8; u++) {
            float4 c = sh[j0 + u];
            d[u] = fmaf(c.x, m2x, fmaf(c.y, m2y, fmaf(c.z, m2z, c.w)));
        }
        #pragma unroll
        for (int u = 0; u < 8; u++) {
            if (d[u] < thresh) {
                float t = d[u];
                #pragma unroll
                for (int s = 0; s < KNN; s++) {
                    float lo = fminf(a[s], t);
                    t = fmaxf(a[s], t);
                    a[s] = lo;
                }
                thresh = a[KNN - 1];
                if (cnt < CAP) buf[cnt * BTHR + tid] = (unsigned short)(j0 + u);
                cnt++;
            }
        }
    }

    // collect the winning local indices (first KNN in index order with d <= thresh)
    unsigned short ids[KNN];
    int w = 0;
    int m = cnt < CAP ? cnt : CAP;
    for (int t = 0; t < m && w < KNN; t++) {
        unsigned short id = buf[t * BTHR + tid];
        float4 c = sh[id];
        float d = fmaf(c.x, m2x, fmaf(c.y, m2y, fmaf(c.z, m2z, c.w)));
        if (d <= thresh) ids[w++] = id;
    }
    if (cnt > CAP) {            // exact rescan fallback (never taken in practice)
        w = 0;
        for (int j = 0; j < LSPL && w < KNN; j++) {
            float4 c = sh[j];
            float d = fmaf(c.x, m2x, fmaf(c.y, m2y, fmaf(c.z, m2z, c.w)));
            if (d <= thresh) ids[w++] = (unsigned short)j;
        }
    }
    while (w < KNN) ids[w++] = ids[0];   // safety (unreachable: LSPL >= KNN)

    // build sorted u64 keys (ord(d)<<32 | global_idx) via 10-slot chain
    unsigned long long k[KNN];
    #pragma unroll
    for (int s = 0; s < KNN; s++) k[s] = 0xFFFFFFFFFFFFFFFFull;
    #pragma unroll
    for (int t = 0; t < KNN; t++) {
        unsigned short id = ids[t];
        float4 c = sh[id];
        float d = fmaf(c.x, m2x, fmaf(c.y, m2y, fmaf(c.z, m2z, c.w)));
        unsigned long long key =
            ((unsigned long long)f2ord(d) << 32) | (unsigned)(jbase + id);
        #pragma unroll
        for (int s = 0; s < KNN; s++) {
            unsigned long long lo = (k[s] < key) ? k[s] : key;
            key = (k[s] < key) ? key : k[s];
            k[s] = lo;
        }
    }
    #pragma unroll
    for (int s = 0; s < KNN; s++) g_part[pair][spl][s][n] = k[s];
}

// ---------------- kernel 3: merge partials + votes + plane min + output ----------------
__global__ void merge_kernel(float* __restrict__ out, int out_size) {
    int i = blockIdx.x * blockDim.x + threadIdx.x;
    if (i >= O_ * N_) return;
    int b = i / N_;
    int n = i % N_;
    float4 q = g_pip4[i];
    float m2x = -2.f * q.x;  (void)m2x;

    float sd = q.z;                        // plane signed distance
    #pragma unroll 1
    for (int oi = 0; oi < 3; oi++) {
        int pair = b * 3 + oi;
        int o = oi + (oi >= b ? 1 : 0);
        unsigned long long A[KNN], B[KNN], K[KNN];
        #pragma unroll
        for (int s = 0; s < KNN; s++) {
            A[s] = g_part[pair][0][s][n];
            B[s] = g_part[pair][1][s][n];
        }
        // shift-register merge: take 10 smallest of A∪B
        #pragma unroll
        for (int s = 0; s < KNN; s++) {
            bool ta = A[0] <= B[0];
            K[s] = ta ? A[0] : B[0];
            #pragma unroll
            for (int t = 0; t < KNN - 1; t++) {
                unsigned long long an = A[t + 1], bn = B[t + 1];
                A[t] = ta ? an : A[t];
                B[t] = ta ? B[t] : bn;
            }
            if (ta) A[KNN - 1] = 0xFFFFFFFFFFFFFFFFull;
            else    B[KNN - 1] = 0xFFFFFFFFFFFFFFFFull;
        }
        // votes over the 10 NN
        int votes = 0;
        const float4* pp = g_pip4 + o * N_;
        const float4* nr = g_nrm4 + o * N_;
        #pragma unroll
        for (int s = 0; s < KNN; s++) {
            unsigned id = (unsigned)(K[s] & 0xFFFFFFFFu);
            float4 c  = __ldg(&pp[id]);
            float4 nm = __ldg(&nr[id]);
            float dt = (c.x - q.x) * nm.x + (c.y - q.y) * nm.y + (c.z - q.z) * nm.z;
            votes += (dt > 0.f) ? 1 : 0;
        }
        float dmin = ord2f((unsigned)(K[0] >> 32));
        float D = q.w + dmin;
        float d0 = sqrtf(fmaxf(D, 0.f));
        float s0 = (votes > 8) ? -d0 : d0;
        sd = fminf(sd, s0);
    }
    out[i] = sd;
    if (out_size >= 2 * O_ * N_)
        out[O_ * N_ + i] = (sd < -TOLC) ? 1.0f : 0.0f;
}

// ---------------- launch ----------------
extern "C" void kernel_launch(void* const* d_in, const int* in_sizes, int n_in,
                              void* d_out, int out_size) {
    const float* points  = nullptr;
    const float* T_obj   = nullptr;
    const float* T_plane = nullptr;
    for (int i = 0; i < n_in; i++) {
        if (in_sizes[i] == O_ * N_ * 6) points  = (const float*)d_in[i];
        else if (in_sizes[i] == 64)     T_obj   = (const float*)d_in[i];
        else if (in_sizes[i] == 16)     T_plane = (const float*)d_in[i];
    }

    transform_kernel<<<(O_ * N_ + 255) / 256, 256>>>(points, T_obj, T_plane);

    int smem = LSPL * (int)sizeof(float4) + CAP * BTHR * (int)sizeof(unsigned short);
    (void)cudaFuncSetAttribute(knn_partial_kernel,
                               cudaFuncAttributeMaxDynamicSharedMemorySize, smem);
    knn_partial_kernel<<<dim3(N_ / BTHR, O_ * 3, NSPL), BTHR, smem>>>();

    merge_kernel<<<(O_ * N_ + 127) / 128, 128>>>((float*)d_out, out_size);
}

// round 5
// speedup vs baseline: 2.1241x; 1.1084x over previous
#include <cuda_runtime.h>
#include <cuda_bf16.h>

#define O_    4
#define N_    3072
#define KNN   10
#define TOLC  0.01f
#define FMAXV 3.402823466e+38f
#define NSPL  2              // candidate splits
#define LSPL  (N_ / NSPL)    // 1536 candidates per split
#define CAP   120            // per-thread trigger buffer entries
#define BTHR  128            // threads per knn block
#define NS    4096           // bitonic sort size (N_ padded)

// ---------------- device scratch (no allocations allowed) ----------------
__device__ float4 g_pip4[O_ * N_];                 // (x, y, z, |p|^2)
__device__ float4 g_nrm4[O_ * N_];                 // raw normal
__device__ unsigned short g_perm[O_][N_];          // Morton-order query permutation
__device__ unsigned long long g_part[O_ * 3][NSPL][KNN][N_];  // sorted partial keys

// ordered-float helpers
__device__ __forceinline__ unsigned f2ord(float f) {
    unsigned b = __float_as_uint(f);
    return b ^ ((unsigned)(((int)b) >> 31) | 0x80000000u);
}
__device__ __forceinline__ float ord2f(unsigned u) {
    int ib = (u & 0x80000000u) ? (int)(u ^ 0x80000000u) : ~(int)u;
    return __int_as_float(ib);
}

// ---------------- kernel 1: prep + transform fused ----------------
__global__ void transform_kernel(const float* __restrict__ points,
                                 const float* __restrict__ T_obj,
                                 const float* __restrict__ T_plane) {
    int i = blockIdx.x * blockDim.x + threadIdx.x;
    if (i >= O_ * N_) return;
    int o = i / N_;

    float Rp[9], tp[3];
    #pragma unroll
    for (int r = 0; r < 3; r++) {
        #pragma unroll
        for (int c = 0; c < 3; c++) Rp[r * 3 + c] = __ldg(&T_plane[r * 4 + c]);
        tp[r] = __ldg(&T_plane[r * 4 + 3]);
    }
    const float* To = T_obj + o * 16;
    float R[3][3], tr[3];
    #pragma unroll
    for (int r = 0; r < 3; r++) {
        R[r][0] = Rp[0 + r] * To[0] + Rp[3 + r] * To[4] + Rp[6 + r] * To[8];
        R[r][1] = Rp[0 + r] * To[1] + Rp[3 + r] * To[5] + Rp[6 + r] * To[9];
        R[r][2] = Rp[0 + r] * To[2] + Rp[3 + r] * To[6] + Rp[6 + r] * To[10];
        tr[r]   = Rp[0 + r] * (To[3] - tp[0]) + Rp[3 + r] * (To[7] - tp[1])
                + Rp[6 + r] * (To[11] - tp[2]);
    }

    const float* p = points + (size_t)i * 6;
    float x = p[0], y = p[1], z = p[2];
    float px = fmaf(R[0][0], x, fmaf(R[0][1], y, fmaf(R[0][2], z, tr[0])));
    float py = fmaf(R[1][0], x, fmaf(R[1][1], y, fmaf(R[1][2], z, tr[1])));
    float pz = fmaf(R[2][0], x, fmaf(R[2][1], y, fmaf(R[2][2], z, tr[2])));
    float rr = px * px + py * py + pz * pz;
    g_pip4[i] = make_float4(px, py, pz, rr);
    g_nrm4[i] = make_float4(p[3], p[4], p[5], 0.f);
}

// ---------------- kernel 1b: Morton-order permutation per object ----------------
__device__ __forceinline__ unsigned q3(float v) {
    int q = (int)floorf((v + 3.f) * (8.f / 6.f));
    return (unsigned)(q < 0 ? 0 : (q > 7 ? 7 : q));
}
__device__ __forceinline__ unsigned spread3(unsigned x) {
    return (x & 1u) | ((x & 2u) << 2) | ((x & 4u) << 4);
}
__global__ void __launch_bounds__(1024) sortperm_kernel() {
    __shared__ unsigned sk[NS];
    int o = blockIdx.x;
    for (int i = threadIdx.x; i < NS; i += blockDim.x) {
        unsigned key = 0xFFFFFFFFu;
        if (i < N_) {
            float4 p = g_pip4[o * N_ + i];
            unsigned m = spread3(q3(p.x)) | (spread3(q3(p.y)) << 1)
                       | (spread3(q3(p.z)) << 2);
            key = (m << 12) | (unsigned)i;
        }
        sk[i] = key;
    }
    __syncthreads();
    for (int k = 2; k <= NS; k <<= 1) {
        for (int j = k >> 1; j > 0; j >>= 1) {
            for (int i = threadIdx.x; i < NS; i += blockDim.x) {
                int ixj = i ^ j;
                if (ixj > i) {
                    unsigned a = sk[i], b = sk[ixj];
                    bool up = ((i & k) == 0);
                    if ((a > b) == up) { sk[i] = b; sk[ixj] = a; }
                }
            }
            __syncthreads();
        }
    }
    for (int i = threadIdx.x; i < N_; i += blockDim.x)
        g_perm[o][i] = (unsigned short)(sk[i] & 0xFFFu);
}

// ---------------- kernel 2: partial exact top-10 over one candidate split ----------------
// blockIdx = (query chunk, pair, split); lanes hold Morton-adjacent queries
__global__ void __launch_bounds__(BTHR) knn_partial_kernel() {
    extern __shared__ float4 sh[];                      // LSPL candidate float4
    unsigned short* buf = (unsigned short*)(sh + LSPL); // buf[c*BTHR + tid]
    int pair = blockIdx.y;
    int spl  = blockIdx.z;
    int b  = pair / 3;
    int oi = pair % 3;
    int o  = oi + (oi >= b ? 1 : 0);
    int tid = threadIdx.x;
    int n  = g_perm[b][blockIdx.x * BTHR + tid];        // original query index
    int jbase = spl * LSPL;

    const float4* cand = g_pip4 + o * N_ + jbase;
    for (int i = tid; i < LSPL; i += BTHR) sh[i] = cand[i];
    __syncthreads();

    float4 q = g_pip4[b * N_ + n];
    float m2x = -2.f * q.x, m2y = -2.f * q.y, m2z = -2.f * q.z;

    float a[KNN];
    #pragma unroll
    for (int s = 0; s < KNN; s++) a[s] = FMAXV;
    float thresh = FMAXV;
    int cnt = 0;

    #pragma unroll 1
    for (int j0 = 0; j0 < LSPL; j0 += 8) {
        float d[8];
        #pragma unroll
        for (int u = 0; u < 8; u++) {
            float4 c = sh[j0 + u];
            d[u] = fmaf(c.x, m2x, fmaf(c.y, m2y, fmaf(c.z, m2z, c.w)));
        }
        #pragma unroll
        for (int u = 0; u < 8; u++) {
            if (d[u] < thresh) {
                float t = d[u];
                #pragma unroll
                for (int s = 0; s < KNN; s++) {
                    float lo = fminf(a[s], t);
                    t = fmaxf(a[s], t);
                    a[s] = lo;
                }
                thresh = a[KNN - 1];
                if (cnt < CAP) buf[cnt * BTHR + tid] = (unsigned short)(j0 + u);
                cnt++;
            }
        }
    }

    // collect winning local indices (first KNN in index order with d <= thresh)
    unsigned short ids[KNN];
    int w = 0;
    int m = cnt < CAP ? cnt : CAP;
    for (int t = 0; t < m && w < KNN; t++) {
        unsigned short id = buf[t * BTHR + tid];
        float4 c = sh[id];
        float d = fmaf(c.x, m2x, fmaf(c.y, m2y, fmaf(c.z, m2z, c.w)));
        if (d <= thresh) ids[w++] = id;
    }
    if (cnt > CAP) {            // exact rescan fallback (never taken in practice)
        w = 0;
        for (int j = 0; j < LSPL && w < KNN; j++) {
            float4 c = sh[j];
            float d = fmaf(c.x, m2x, fmaf(c.y, m2y, fmaf(c.z, m2z, c.w)));
            if (d <= thresh) ids[w++] = (unsigned short)j;
        }
    }
    while (w < KNN) ids[w++] = ids[0];   // safety (unreachable: LSPL >= KNN)

    // build sorted u64 keys (ord(d)<<32 | global_idx)
    unsigned long long k[KNN];
    #pragma unroll
    for (int s = 0; s < KNN; s++) k[s] = 0xFFFFFFFFFFFFFFFFull;
    #pragma unroll
    for (int t = 0; t < KNN; t++) {
        unsigned short id = ids[t];
        float4 c = sh[id];
        float d = fmaf(c.x, m2x, fmaf(c.y, m2y, fmaf(c.z, m2z, c.w)));
        unsigned long long key =
            ((unsigned long long)f2ord(d) << 32) | (unsigned)(jbase + id);
        #pragma unroll
        for (int s = 0; s < KNN; s++) {
            unsigned long long lo = (k[s] < key) ? k[s] : key;
            key = (k[s] < key) ? key : k[s];
            k[s] = lo;
        }
    }
    #pragma unroll
    for (int s = 0; s < KNN; s++) g_part[pair][spl][s][n] = k[s];
}

// ---------------- kernel 3: merge partials + votes + plane min + output ----------------
__global__ void merge_kernel(float* __restrict__ out, int out_size) {
    int i = blockIdx.x * blockDim.x + threadIdx.x;
    if (i >= O_ * N_) return;
    int b = i / N_;
    int n = i % N_;
    float4 q = g_pip4[i];

    float sd = q.z;                        // plane signed distance
    #pragma unroll 1
    for (int oi = 0; oi < 3; oi++) {
        int pair = b * 3 + oi;
        int o = oi + (oi >= b ? 1 : 0);
        unsigned long long A[KNN], B[KNN], K[KNN];
        #pragma unroll
        for (int s = 0; s < KNN; s++) {
            A[s] = g_part[pair][0][s][n];
            B[s] = g_part[pair][1][s][n];
        }
        #pragma unroll
        for (int s = 0; s < KNN; s++) {
            bool ta = A[0] <= B[0];
            K[s] = ta ? A[0] : B[0];
            #pragma unroll
            for (int t = 0; t < KNN - 1; t++) {
                unsigned long long an = A[t + 1], bn = B[t + 1];
                A[t] = ta ? an : A[t];
                B[t] = ta ? B[t] : bn;
            }
            if (ta) A[KNN - 1] = 0xFFFFFFFFFFFFFFFFull;
            else    B[KNN - 1] = 0xFFFFFFFFFFFFFFFFull;
        }
        int votes = 0;
        const float4* pp = g_pip4 + o * N_;
        const float4* nr = g_nrm4 + o * N_;
        #pragma unroll
        for (int s = 0; s < KNN; s++) {
            unsigned id = (unsigned)(K[s] & 0xFFFFFFFFu);
            float4 c  = __ldg(&pp[id]);
            float4 nm = __ldg(&nr[id]);
            float dt = (c.x - q.x) * nm.x + (c.y - q.y) * nm.y + (c.z - q.z) * nm.z;
            votes += (dt > 0.f) ? 1 : 0;
        }
        float dmin = ord2f((unsigned)(K[0] >> 32));
        float D = q.w + dmin;
        float d0 = sqrtf(fmaxf(D, 0.f));
        float s0 = (votes > 8) ? -d0 : d0;
        sd = fminf(sd, s0);
    }
    out[i] = sd;
    if (out_size >= 2 * O_ * N_)
        out[O_ * N_ + i] = (sd < -TOLC) ? 1.0f : 0.0f;
}

// ---------------- launch ----------------
extern "C" void kernel_launch(void* const* d_in, const int* in_sizes, int n_in,
                              void* d_out, int out_size) {
    const float* points  = nullptr;
    const float* T_obj   = nullptr;
    const float* T_plane = nullptr;
    for (int i = 0; i < n_in; i++) {
        if (in_sizes[i] == O_ * N_ * 6) points  = (const float*)d_in[i];
        else if (in_sizes[i] == 64)     T_obj   = (const float*)d_in[i];
        else if (in_sizes[i] == 16)     T_plane = (const float*)d_in[i];
    }

    transform_kernel<<<(O_ * N_ + 255) / 256, 256>>>(points, T_obj, T_plane);
    sortperm_kernel<<<O_, 1024>>>();

    int smem = LSPL * (int)sizeof(float4) + CAP * BTHR * (int)sizeof(unsigned short);
    (void)cudaFuncSetAttribute(knn_partial_kernel,
                               cudaFuncAttributeMaxDynamicSharedMemorySize, smem);
    knn_partial_kernel<<<dim3(N_ / BTHR, O_ * 3, NSPL), BTHR, smem>>>();

    merge_kernel<<<(O_ * N_ + 127) / 128, 128>>>((float*)d_out, out_size);
}

// round 7
// speedup vs baseline: 2.8738x; 1.3530x over previous
#include <cuda_runtime.h>
#include <cuda_bf16.h>

#define O_    4
#define N_    3072
#define KNN   10
#define TOLC  0.01f
#define FMAXV 3.402823466e+38f
#define BTHR  128            // threads per knn block
#define CAP   120            // per-thread commit buffer (mean ~72, ~5.6 sigma)
#define SEED  64             // branchy seed prefix
#define CH1   64             // chunk size while j < CHSW (tight threshold early)
#define CH2   256            // chunk size after
#define CHSW  1024

// ---------------- device scratch (no allocations allowed) ----------------
__device__ float4 g_pip4[O_ * N_];     // (x, y, z, |p|^2)
__device__ float4 g_nrm4[O_ * N_];     // raw normal
__device__ float  g_scr[O_][3][N_];    // signed nearest distance per (b, other-idx, n)

// ---------------- kernel 1: prep + transform fused ----------------
__global__ void transform_kernel(const float* __restrict__ points,
                                 const float* __restrict__ T_obj,
                                 const float* __restrict__ T_plane) {
    int i = blockIdx.x * blockDim.x + threadIdx.x;
    if (i >= O_ * N_) return;
    int o = i / N_;

    float Rp[9], tp[3];
    #pragma unroll
    for (int r = 0; r < 3; r++) {
        #pragma unroll
        for (int c = 0; c < 3; c++) Rp[r * 3 + c] = __ldg(&T_plane[r * 4 + c]);
        tp[r] = __ldg(&T_plane[r * 4 + 3]);
    }
    const float* To = T_obj + o * 16;
    // inv(T_plane) rigid: [Rp^T | -Rp^T tp]
    float R[3][3], tr[3];
    #pragma unroll
    for (int r = 0; r < 3; r++) {
        R[r][0] = Rp[0 + r] * To[0] + Rp[3 + r] * To[4] + Rp[6 + r] * To[8];
        R[r][1] = Rp[0 + r] * To[1] + Rp[3 + r] * To[5] + Rp[6 + r] * To[9];
        R[r][2] = Rp[0 + r] * To[2] + Rp[3 + r] * To[6] + Rp[6 + r] * To[10];
        tr[r]   = Rp[0 + r] * (To[3] - tp[0]) + Rp[3 + r] * (To[7] - tp[1])
                + Rp[6 + r] * (To[11] - tp[2]);
    }

    const float* p = points + (size_t)i * 6;
    float x = p[0], y = p[1], z = p[2];
    float px = fmaf(R[0][0], x, fmaf(R[0][1], y, fmaf(R[0][2], z, tr[0])));
    float py = fmaf(R[1][0], x, fmaf(R[1][1], y, fmaf(R[1][2], z, tr[1])));
    float pz = fmaf(R[2][0], x, fmaf(R[2][1], y, fmaf(R[2][2], z, tr[2])));
    float rr = px * px + py * py + pz * pz;
    g_pip4[i] = make_float4(px, py, pz, rr);
    g_nrm4[i] = make_float4(p[3], p[4], p[5], 0.f);
}

// ---------------- kernel 2: exact top-10 per (b, o!=b, n), collect-then-replay ----------------
__global__ void __launch_bounds__(BTHR) knn_kernel() {
    extern __shared__ float4 sh[];
    unsigned* buf = (unsigned*)(sh + N_);          // buf[slot*BTHR + tid]
    int pair = blockIdx.y;
    int b  = pair / 3;
    int oi = pair - b * 3;
    int o  = oi + (oi >= b ? 1 : 0);
    int tid = threadIdx.x;
    int n  = blockIdx.x * BTHR + tid;

    const float4* cand = g_pip4 + o * N_;
    for (int i = tid; i < N_; i += BTHR) sh[i] = cand[i];
    __syncthreads();

    float4 q = g_pip4[b * N_ + n];
    float m2x = -2.f * q.x, m2y = -2.f * q.y, m2z = -2.f * q.z;

    float a[KNN];
    #pragma unroll
    for (int s = 0; s < KNN; s++) a[s] = FMAXV;
    float thresh = FMAXV;
    int cnt = 0;

    // ---- phase 1: seed chain over first SEED candidates (branchy, small) ----
    #pragma unroll 1
    for (int j = 0; j < SEED; j++) {
        float4 c = sh[j];
        float d = fmaf(c.x, m2x, fmaf(c.y, m2y, fmaf(c.z, m2z, c.w)));
        if (d < thresh) {
            int slot = cnt < CAP - 1 ? cnt : CAP - 1;
            buf[slot * BTHR + tid] = (unsigned)j;
            cnt++;
            float t = d;
            #pragma unroll
            for (int s = 0; s < KNN; s++) {
                float lo = fminf(a[s], t);
                t = fmaxf(a[s], t);
                a[s] = lo;
            }
            thresh = a[KNN - 1];
        }
    }
    int start = cnt < CAP ? cnt : CAP;

    // ---- phase 2: branchless collect + per-chunk replay (chunk 64 early, 256 late) ----
    #pragma unroll 1
    for (int j0 = SEED; j0 < N_; ) {
        int cs = j0 < CHSW ? CH1 : CH2;
        int jend = j0 + cs < N_ ? j0 + cs : N_;
        #pragma unroll 1
        for (int jj = j0; jj < jend; jj += 8) {
            float d[8];
            #pragma unroll
            for (int u = 0; u < 8; u++) {
                float4 c = sh[jj + u];
                d[u] = fmaf(c.x, m2x, fmaf(c.y, m2y, fmaf(c.z, m2z, c.w)));
            }
            #pragma unroll
            for (int u = 0; u < 8; u++) {
                int slot = cnt < CAP - 1 ? cnt : CAP - 1;
                buf[slot * BTHR + tid] = (unsigned)(jj + u);  // unconditional
                cnt += (d[u] < thresh) ? 1 : 0;               // commit if kept
            }
        }
        // replay newly committed entries, refresh threshold
        int stop = cnt < CAP ? cnt : CAP;
        #pragma unroll 1
        for (int t = start; ; t++) {
            bool act = t < stop;
            if (!__any_sync(0xFFFFFFFFu, act)) break;
            if (act) {
                unsigned id = buf[t * BTHR + tid];
                float4 c = sh[id];
                float d = fmaf(c.x, m2x, fmaf(c.y, m2y, fmaf(c.z, m2z, c.w)));
                if (d < thresh) {
                    float v = d;
                    #pragma unroll
                    for (int s = 0; s < KNN; s++) {
                        float lo = fminf(a[s], v);
                        v = fmaxf(a[s], v);
                        a[s] = lo;
                    }
                    thresh = a[KNN - 1];
                }
            }
        }
        start = stop;
        j0 = jend;
    }

    // ---- phase 3: final id selection ----
    unsigned ids[KNN];
    int w = 0;
    if (cnt < CAP) {   // all committed slots intact (slot CAP-1 never trusted)
        for (int t = 0; t < cnt && w < KNN; t++) {
            unsigned id = buf[t * BTHR + tid];
            float4 c = sh[id];
            float d = fmaf(c.x, m2x, fmaf(c.y, m2y, fmaf(c.z, m2z, c.w)));
            if (d <= thresh) ids[w++] = id;
        }
    } else {
        // overflow fallback: exact full redo (P ~ 1e-8 per thread)
        #pragma unroll
        for (int s = 0; s < KNN; s++) a[s] = FMAXV;
        thresh = FMAXV;
        for (int j = 0; j < N_; j++) {
            float4 c = sh[j];
            float d = fmaf(c.x, m2x, fmaf(c.y, m2y, fmaf(c.z, m2z, c.w)));
            if (d < thresh) {
                float v = d;
                #pragma unroll
                for (int s = 0; s < KNN; s++) {
                    float lo = fminf(a[s], v);
                    v = fmaxf(a[s], v);
                    a[s] = lo;
                }
                thresh = a[KNN - 1];
            }
        }
        for (int j = 0; j < N_ && w < KNN; j++) {
            float4 c = sh[j];
            float d = fmaf(c.x, m2x, fmaf(c.y, m2y, fmaf(c.z, m2z, c.w)));
            if (d <= thresh) ids[w++] = (unsigned)j;
        }
    }
    while (w < KNN) ids[w++] = ids[0];   // safety (unreachable)

    // ---- phase 4: exact d0 + inside votes ----
    float D = q.w + a[0];
    float d0 = sqrtf(fmaxf(D, 0.f));

    int votes = 0;
    const float4* nrm = g_nrm4 + o * N_;
    #pragma unroll
    for (int s = 0; s < KNN; s++) {
        unsigned id = ids[s];
        float4 c  = sh[id];
        float4 nm = __ldg(&nrm[id]);
        float dt = (c.x - q.x) * nm.x + (c.y - q.y) * nm.y + (c.z - q.z) * nm.z;
        votes += (dt > 0.f) ? 1 : 0;
    }
    float sd = (votes > 8) ? -d0 : d0;   // sum(insides) > 0.8*k -> >= 9
    g_scr[b][oi][n] = sd;
}

// ---------------- kernel 3: min over other objects + plane, write out ----------------
__global__ void finalize_kernel(float* __restrict__ out, int out_size) {
    int i = blockIdx.x * blockDim.x + threadIdx.x;
    if (i >= O_ * N_) return;
    int b = i / N_;
    int n = i % N_;
    float sd = g_pip4[i].z;                 // plane signed distance = pip.z
    sd = fminf(sd, g_scr[b][0][n]);
    sd = fminf(sd, g_scr[b][1][n]);
    sd = fminf(sd, g_scr[b][2][n]);
    out[i] = sd;
    if (out_size >= 2 * O_ * N_)
        out[O_ * N_ + i] = (sd < -TOLC) ? 1.0f : 0.0f;
}

// ---------------- launch ----------------
extern "C" void kernel_launch(void* const* d_in, const int* in_sizes, int n_in,
                              void* d_out, int out_size) {
    const float* points  = nullptr;
    const float* T_obj   = nullptr;
    const float* T_plane = nullptr;
    for (int i = 0; i < n_in; i++) {
        if (in_sizes[i] == O_ * N_ * 6) points  = (const float*)d_in[i];
        else if (in_sizes[i] == 64)     T_obj   = (const float*)d_in[i];
        else if (in_sizes[i] == 16)     T_plane = (const float*)d_in[i];
    }

    transform_kernel<<<(O_ * N_ + 255) / 256, 256>>>(points, T_obj, T_plane);

    int smem = N_ * (int)sizeof(float4) + CAP * BTHR * (int)sizeof(unsigned);
    (void)cudaFuncSetAttribute(knn_kernel,
                               cudaFuncAttributeMaxDynamicSharedMemorySize, smem);
    knn_kernel<<<dim3(N_ / BTHR, O_ * 3), BTHR, smem>>>();

    finalize_kernel<<<(O_ * N_ + 255) / 256, 256>>>((float*)d_out, out_size);
}

// round 8
// speedup vs baseline: 2.8785x; 1.0016x over previous
#include <cuda_runtime.h>
#include <cuda_bf16.h>

#define O_    4
#define N_    3072
#define HALF  1536           // candidates per thread (half the tile)
#define KNN   10
#define TOLC  0.01f
#define FMAXV 3.402823466e+38f
#define BTHR  256            // threads per knn block (2 threads per query)
#define QPB   128            // queries per block
#define CAP   112            // per-thread commit buffer (mean ~57, >5 sigma)
#define SEED  64             // branchy seed prefix (local)
#define CH1   64             // chunk size while local j < CHSW
#define CH2   256
#define CHSW  512

// ---------------- device scratch (no allocations allowed) ----------------
__device__ float4 g_pip4[O_ * N_];     // (x, y, z, |p|^2)
__device__ float4 g_nrm4[O_ * N_];     // raw normal
__device__ float  g_scr[O_][3][N_];    // signed nearest distance per (b, other-idx, n)

// ordered-float helpers
__device__ __forceinline__ unsigned f2ord(float f) {
    unsigned b = __float_as_uint(f);
    return b ^ ((unsigned)(((int)b) >> 31) | 0x80000000u);
}
__device__ __forceinline__ float ord2f(unsigned u) {
    int ib = (u & 0x80000000u) ? (int)(u ^ 0x80000000u) : ~(int)u;
    return __int_as_float(ib);
}

// ---------------- kernel 1: prep + transform fused ----------------
__global__ void transform_kernel(const float* __restrict__ points,
                                 const float* __restrict__ T_obj,
                                 const float* __restrict__ T_plane) {
    int i = blockIdx.x * blockDim.x + threadIdx.x;
    if (i >= O_ * N_) return;
    int o = i / N_;

    float Rp[9], tp[3];
    #pragma unroll
    for (int r = 0; r < 3; r++) {
        #pragma unroll
        for (int c = 0; c < 3; c++) Rp[r * 3 + c] = __ldg(&T_plane[r * 4 + c]);
        tp[r] = __ldg(&T_plane[r * 4 + 3]);
    }
    const float* To = T_obj + o * 16;
    float R[3][3], tr[3];
    #pragma unroll
    for (int r = 0; r < 3; r++) {
        R[r][0] = Rp[0 + r] * To[0] + Rp[3 + r] * To[4] + Rp[6 + r] * To[8];
        R[r][1] = Rp[0 + r] * To[1] + Rp[3 + r] * To[5] + Rp[6 + r] * To[9];
        R[r][2] = Rp[0 + r] * To[2] + Rp[3 + r] * To[6] + Rp[6 + r] * To[10];
        tr[r]   = Rp[0 + r] * (To[3] - tp[0]) + Rp[3 + r] * (To[7] - tp[1])
                + Rp[6 + r] * (To[11] - tp[2]);
    }

    const float* p = points + (size_t)i * 6;
    float x = p[0], y = p[1], z = p[2];
    float px = fmaf(R[0][0], x, fmaf(R[0][1], y, fmaf(R[0][2], z, tr[0])));
    float py = fmaf(R[1][0], x, fmaf(R[1][1], y, fmaf(R[1][2], z, tr[1])));
    float pz = fmaf(R[2][0], x, fmaf(R[2][1], y, fmaf(R[2][2], z, tr[2])));
    float rr = px * px + py * py + pz * pz;
    g_pip4[i] = make_float4(px, py, pz, rr);
    g_nrm4[i] = make_float4(p[3], p[4], p[5], 0.f);
}

// ---------------- kernel 2: split-scan top-10 + block-local merge ----------------
// smem: [0,48K) candidates float4 ; [48K,+56K) commit buffer u16 [CAP][BTHR],
//       later reused as u64 key scratch [KNN][BTHR] (20KB)
__global__ void __launch_bounds__(BTHR) knn_kernel() {
    extern __shared__ float4 sh[];
    unsigned short* buf = (unsigned short*)(sh + N_);
    unsigned long long* scr = (unsigned long long*)(sh + N_);   // aliased; used post-sync
    int pair = blockIdx.y;
    int b  = pair / 3;
    int oi = pair - b * 3;
    int o  = oi + (oi >= b ? 1 : 0);
    int tid = threadIdx.x;
    int qid = tid & (QPB - 1);
    int half = tid >> 7;
    int n  = blockIdx.x * QPB + qid;
    int jbase = half * HALF;

    const float4* cand = g_pip4 + o * N_;
    for (int i = tid; i < N_; i += BTHR) sh[i] = cand[i];
    __syncthreads();

    const float4* cs = sh + jbase;       // this thread's half, local idx 0..HALF-1
    float4 q = g_pip4[b * N_ + n];
    float m2x = -2.f * q.x, m2y = -2.f * q.y, m2z = -2.f * q.z;

    float a[KNN];
    #pragma unroll
    for (int s = 0; s < KNN; s++) a[s] = FMAXV;
    float thresh = FMAXV;
    int cnt = 0;

    // ---- phase 1: seed chain (branchy, small) ----
    #pragma unroll 1
    for (int j = 0; j < SEED; j++) {
        float4 c = cs[j];
        float d = fmaf(c.x, m2x, fmaf(c.y, m2y, fmaf(c.z, m2z, c.w)));
        if (d < thresh) {
            int slot = cnt < CAP - 1 ? cnt : CAP - 1;
            buf[slot * BTHR + tid] = (unsigned short)j;
            cnt++;
            float t = d;
            #pragma unroll
            for (int s = 0; s < KNN; s++) {
                float lo = fminf(a[s], t);
                t = fmaxf(a[s], t);
                a[s] = lo;
            }
            thresh = a[KNN - 1];
        }
    }
    int start = cnt < CAP ? cnt : CAP;

    // ---- phase 2: branchless collect + per-chunk replay ----
    #pragma unroll 1
    for (int j0 = SEED; j0 < HALF; ) {
        int cspan = j0 < CHSW ? CH1 : CH2;
        int jend = j0 + cspan < HALF ? j0 + cspan : HALF;
        #pragma unroll 1
        for (int jj = j0; jj < jend; jj += 8) {
            float d[8];
            #pragma unroll
            for (int u = 0; u < 8; u++) {
                float4 c = cs[jj + u];
                d[u] = fmaf(c.x, m2x, fmaf(c.y, m2y, fmaf(c.z, m2z, c.w)));
            }
            #pragma unroll
            for (int u = 0; u < 8; u++) {
                int slot = cnt < CAP - 1 ? cnt : CAP - 1;
                buf[slot * BTHR + tid] = (unsigned short)(jj + u);  // unconditional
                cnt += (d[u] < thresh) ? 1 : 0;
            }
        }
        int stop = cnt < CAP ? cnt : CAP;
        #pragma unroll 1
        for (int t = start; ; t++) {
            bool act = t < stop;
            if (!__any_sync(0xFFFFFFFFu, act)) break;
            if (act) {
                unsigned id = buf[t * BTHR + tid];
                float4 c = cs[id];
                float d = fmaf(c.x, m2x, fmaf(c.y, m2y, fmaf(c.z, m2z, c.w)));
                if (d < thresh) {
                    float v = d;
                    #pragma unroll
                    for (int s = 0; s < KNN; s++) {
                        float lo = fminf(a[s], v);
                        v = fmaxf(a[s], v);
                        a[s] = lo;
                    }
                    thresh = a[KNN - 1];
                }
            }
        }
        start = stop;
        j0 = jend;
    }

    // ---- phase 3: final id selection for this half ----
    unsigned ids[KNN];
    int w = 0;
    if (cnt < CAP) {
        for (int t = 0; t < cnt && w < KNN; t++) {
            unsigned id = buf[t * BTHR + tid];
            float4 c = cs[id];
            float d = fmaf(c.x, m2x, fmaf(c.y, m2y, fmaf(c.z, m2z, c.w)));
            if (d <= thresh) ids[w++] = id;
        }
    } else {
        // overflow fallback: exact redo over this half (practically unreachable)
        #pragma unroll
        for (int s = 0; s < KNN; s++) a[s] = FMAXV;
        thresh = FMAXV;
        for (int j = 0; j < HALF; j++) {
            float4 c = cs[j];
            float d = fmaf(c.x, m2x, fmaf(c.y, m2y, fmaf(c.z, m2z, c.w)));
            if (d < thresh) {
                float v = d;
                #pragma unroll
                for (int s = 0; s < KNN; s++) {
                    float lo = fminf(a[s], v);
                    v = fmaxf(a[s], v);
                    a[s] = lo;
                }
                thresh = a[KNN - 1];
            }
        }
        for (int j = 0; j < HALF && w < KNN; j++) {
            float4 c = cs[j];
            float d = fmaf(c.x, m2x, fmaf(c.y, m2y, fmaf(c.z, m2z, c.w)));
            if (d <= thresh) ids[w++] = (unsigned)j;
        }
    }
    while (w < KNN) ids[w++] = ids[0];   // safety (unreachable)

    // ---- phase 4: build sorted u64 keys (ord(d)<<32 | global_id) ----
    unsigned long long k[KNN];
    #pragma unroll
    for (int s = 0; s < KNN; s++) k[s] = 0xFFFFFFFFFFFFFFFFull;
    #pragma unroll
    for (int t = 0; t < KNN; t++) {
        unsigned id = ids[t];
        float4 c = cs[id];
        float d = fmaf(c.x, m2x, fmaf(c.y, m2y, fmaf(c.z, m2z, c.w)));
        unsigned long long key =
            ((unsigned long long)f2ord(d) << 32) | (unsigned)(jbase + id);
        #pragma unroll
        for (int s = 0; s < KNN; s++) {
            unsigned long long lo = (k[s] < key) ? k[s] : key;
            key = (k[s] < key) ? key : k[s];
            k[s] = lo;
        }
    }

    __syncthreads();                     // all buf reads done; safe to alias
    #pragma unroll
    for (int s = 0; s < KNN; s++) scr[s * BTHR + tid] = k[s];
    __syncthreads();

    // ---- phase 5: threads 0..127 merge the two halves, vote, write ----
    if (tid < QPB) {
        unsigned long long A[KNN], B[KNN], K[KNN];
        #pragma unroll
        for (int s = 0; s < KNN; s++) {
            A[s] = scr[s * BTHR + tid];
            B[s] = scr[s * BTHR + tid + QPB];
        }
        #pragma unroll
        for (int s = 0; s < KNN; s++) {
            bool ta = A[0] <= B[0];      // half0 has smaller global ids -> tie ok
            K[s] = ta ? A[0] : B[0];
            #pragma unroll
            for (int t = 0; t < KNN - 1; t++) {
                unsigned long long an = A[t + 1], bn = B[t + 1];
                A[t] = ta ? an : A[t];
                B[t] = ta ? B[t] : bn;
            }
            if (ta) A[KNN - 1] = 0xFFFFFFFFFFFFFFFFull;
            else    B[KNN - 1] = 0xFFFFFFFFFFFFFFFFull;
        }

        float dmin = ord2f((unsigned)(K[0] >> 32));
        float D = q.w + dmin;
        float d0 = sqrtf(fmaxf(D, 0.f));

        int votes = 0;
        const float4* nrm = g_nrm4 + o * N_;
        #pragma unroll
        for (int s = 0; s < KNN; s++) {
            unsigned id = (unsigned)(K[s] & 0xFFFFFFFFu);
            float4 c  = sh[id];
            float4 nm = __ldg(&nrm[id]);
            float dt = (c.x - q.x) * nm.x + (c.y - q.y) * nm.y + (c.z - q.z) * nm.z;
            votes += (dt > 0.f) ? 1 : 0;
        }
        float sd = (votes > 8) ? -d0 : d0;   // sum(insides) > 0.8*k -> >= 9
        g_scr[b][oi][n] = sd;
    }
}

// ---------------- kernel 3: min over other objects + plane, write out ----------------
__global__ void finalize_kernel(float* __restrict__ out, int out_size) {
    int i = blockIdx.x * blockDim.x + threadIdx.x;
    if (i >= O_ * N_) return;
    int b = i / N_;
    int n = i % N_;
    float sd = g_pip4[i].z;                 // plane signed distance = pip.z
    sd = fminf(sd, g_scr[b][0][n]);
    sd = fminf(sd, g_scr[b][1][n]);
    sd = fminf(sd, g_scr[b][2][n]);
    out[i] = sd;
    if (out_size >= 2 * O_ * N_)
        out[O_ * N_ + i] = (sd < -TOLC) ? 1.0f : 0.0f;
}

// ---------------- launch ----------------
extern "C" void kernel_launch(void* const* d_in, const int* in_sizes, int n_in,
                              void* d_out, int out_size) {
    const float* points  = nullptr;
    const float* T_obj   = nullptr;
    const float* T_plane = nullptr;
    for (int i = 0; i < n_in; i++) {
        if (in_sizes[i] == O_ * N_ * 6) points  = (const float*)d_in[i];
        else if (in_sizes[i] == 64)     T_obj   = (const float*)d_in[i];
        else if (in_sizes[i] == 16)     T_plane = (const float*)d_in[i];
    }

    transform_kernel<<<(O_ * N_ + 255) / 256, 256>>>(points, T_obj, T_plane);

    int smem = N_ * (int)sizeof(float4) + CAP * BTHR * (int)sizeof(unsigned short);
    (void)cudaFuncSetAttribute(knn_kernel,
                               cudaFuncAttributeMaxDynamicSharedMemorySize, smem);
    knn_kernel<<<dim3(N_ / QPB, O_ * 3), BTHR, smem>>>();

    finalize_kernel<<<(O_ * N_ + 255) / 256, 256>>>((float*)d_out, out_size);
}